// round 1
// baseline (speedup 1.0000x reference)
#include <cuda_runtime.h>
#include <cuda_bf16.h>

// Shapes (fixed by the problem's setup_inputs): B=128, N=10000, din=64, draw=64, T=8, D=128
#define B_MAX 128
#define N_MAX 10000
#define DIN   64
#define DMODL 128   // D = din + draw

// Scratch (static __device__ — no allocation allowed)
__device__ float    g_E[(size_t)B_MAX * N_MAX];  // leaky(e) per (b,n)
__device__ float    g_C[B_MAX];                  // per-b constant term
__device__ unsigned g_M[B_MAX];                  // encoded running max
__device__ float    g_Mf[B_MAX];                 // decoded max
__device__ float    g_R[B_MAX];                  // 1 / sum(exp)

// Monotone float<->uint encoding so atomicMax on unsigned == float max
__device__ __forceinline__ unsigned enc_f(float f) {
    unsigned u = __float_as_uint(f);
    return (u & 0x80000000u) ? ~u : (u | 0x80000000u);
}
__device__ __forceinline__ float dec_f(unsigned k) {
    return (k & 0x80000000u) ? __uint_as_float(k & 0x7fffffffu)
                             : __uint_as_float(~k);
}

// ---------------------------------------------------------------------------
// 1) prep: c[b] = dot(x[b, node_index, :], a[t, 0:64]); init max scratch.
// ---------------------------------------------------------------------------
__global__ void prep_kernel(const float* __restrict__ x,
                            const float* __restrict__ a,
                            const int*   __restrict__ node_index,
                            const int*   __restrict__ type_index,
                            int B, int N) {
    int b = threadIdx.x;
    if (b >= B) return;
    int ni = node_index[0];
    int t  = type_index[b];
    const float* xp = x + ((size_t)b * N + ni) * DIN;
    const float* ap = a + (size_t)t * DMODL;
    float c = 0.f;
#pragma unroll
    for (int d = 0; d < DIN; ++d) c += xp[d] * ap[d];
    g_C[b] = c;
    g_M[b] = 0u;   // encoded -inf
}

// ---------------------------------------------------------------------------
// 2) main: stream raw_x once. 16 lanes cooperate per n (64 floats = 4/lane,
//    float4, fully coalesced). leaky-relu, store e, masked running max.
// ---------------------------------------------------------------------------
__global__ __launch_bounds__(256)
void main_kernel(const float* __restrict__ raw_x,
                 const float* __restrict__ a,
                 const float* __restrict__ adj_mask,
                 const int*   __restrict__ type_index,
                 int N, int nPerBlock) {
    const int b      = blockIdx.y;
    const int tid    = threadIdx.x;
    const int lane16 = tid & 15;
    const int sub    = tid >> 4;            // 0..15: 16 n's per iteration
    const int n0     = blockIdx.x * nPerBlock;
    const int nEnd   = min(n0 + nPerBlock, N);

    const int t = type_index[b];
    const float* ap = a + (size_t)t * DMODL + DIN + lane16 * 4;
    const float w0 = ap[0], w1 = ap[1], w2 = ap[2], w3 = ap[3];
    const float c  = g_C[b];

    const float* base = raw_x + (size_t)b * N * DIN;
    float*       Eb   = g_E   + (size_t)b * N;

    float lmax = -3.0e38f;
    const int iters = (nEnd - n0 + 15) >> 4;
    for (int it = 0; it < iters; ++it) {
        int n = n0 + it * 16 + sub;
        bool valid = (n < nEnd);
        float4 v = make_float4(0.f, 0.f, 0.f, 0.f);
        if (valid)
            v = *reinterpret_cast<const float4*>(base + (size_t)n * DIN + lane16 * 4);
        float p = v.x * w0 + v.y * w1 + v.z * w2 + v.w * w3;
        p += __shfl_xor_sync(0xffffffffu, p, 8);
        p += __shfl_xor_sync(0xffffffffu, p, 4);
        p += __shfl_xor_sync(0xffffffffu, p, 2);
        p += __shfl_xor_sync(0xffffffffu, p, 1);
        if (valid) {
            float e = c + p;
            e = (e > 0.f) ? e : 0.01f * e;      // leaky relu
            if (lane16 == 0) Eb[n] = e;
            if (adj_mask[n] > 0.f) lmax = fmaxf(lmax, e);
        }
    }

    // block-reduce max, one atomic per block
    lmax = fmaxf(lmax, __shfl_xor_sync(0xffffffffu, lmax, 16));
    lmax = fmaxf(lmax, __shfl_xor_sync(0xffffffffu, lmax, 8));
    lmax = fmaxf(lmax, __shfl_xor_sync(0xffffffffu, lmax, 4));
    lmax = fmaxf(lmax, __shfl_xor_sync(0xffffffffu, lmax, 2));
    lmax = fmaxf(lmax, __shfl_xor_sync(0xffffffffu, lmax, 1));
    __shared__ float sm[8];
    if ((tid & 31) == 0) sm[tid >> 5] = lmax;
    __syncthreads();
    if (tid == 0) {
        float v = sm[0];
#pragma unroll
        for (int i = 1; i < 8; ++i) v = fmaxf(v, sm[i]);
        atomicMax(&g_M[b], enc_f(v));
    }
}

// ---------------------------------------------------------------------------
// 3) sumexp: one block per b over scratch E. S[b] = sum_masked exp(e - m).
// ---------------------------------------------------------------------------
__global__ __launch_bounds__(256)
void sumexp_kernel(const float* __restrict__ adj_mask, int N) {
    const int b = blockIdx.x;
    const float m = dec_f(g_M[b]);
    const float* Eb = g_E + (size_t)b * N;
    float s = 0.f;
    for (int n = threadIdx.x; n < N; n += blockDim.x)
        if (adj_mask[n] > 0.f) s += __expf(Eb[n] - m);
    // block reduce sum
    s += __shfl_xor_sync(0xffffffffu, s, 16);
    s += __shfl_xor_sync(0xffffffffu, s, 8);
    s += __shfl_xor_sync(0xffffffffu, s, 4);
    s += __shfl_xor_sync(0xffffffffu, s, 2);
    s += __shfl_xor_sync(0xffffffffu, s, 1);
    __shared__ float sm[8];
    if ((threadIdx.x & 31) == 0) sm[threadIdx.x >> 5] = s;
    __syncthreads();
    if (threadIdx.x == 0) {
        float tot = sm[0];
#pragma unroll
        for (int i = 1; i < 8; ++i) tot += sm[i];
        g_R[b]  = 1.0f / tot;
        g_Mf[b] = m;
    }
}

// ---------------------------------------------------------------------------
// 4) normalize: out[b,n] = mask>0 ? exp(e-m)/S : 0
// ---------------------------------------------------------------------------
__global__ __launch_bounds__(256)
void norm_kernel(const float* __restrict__ adj_mask,
                 float* __restrict__ out, int N) {
    const int b = blockIdx.y;
    const int n = blockIdx.x * 256 + threadIdx.x;
    if (n >= N) return;
    float o = 0.f;
    if (adj_mask[n] > 0.f)
        o = __expf(g_E[(size_t)b * N + n] - g_Mf[b]) * g_R[b];
    out[(size_t)b * N + n] = o;
}

// ---------------------------------------------------------------------------
extern "C" void kernel_launch(void* const* d_in, const int* in_sizes, int n_in,
                              void* d_out, int out_size) {
    const float* x          = (const float*)d_in[0];
    const float* raw_x      = (const float*)d_in[1];
    const float* a          = (const float*)d_in[2];
    const float* adj_mask   = (const float*)d_in[3];
    const int*   node_index = (const int*)  d_in[4];
    const int*   type_index = (const int*)  d_in[5];
    float* out = (float*)d_out;

    const int N = in_sizes[3];   // adj_mask: (N,)
    const int B = in_sizes[5];   // type_index: (B,)

    prep_kernel<<<1, 128>>>(x, a, node_index, type_index, B, N);

    const int nPerBlock = 400;                       // 25 chunks * 400 = 10000
    const int chunks = (N + nPerBlock - 1) / nPerBlock;
    main_kernel<<<dim3(chunks, B), 256>>>(raw_x, a, adj_mask, type_index, N, nPerBlock);

    sumexp_kernel<<<B, 256>>>(adj_mask, N);

    norm_kernel<<<dim3((N + 255) / 256, B), 256>>>(adj_mask, out, N);
}

// round 4
// speedup vs baseline: 1.7603x; 1.7603x over previous
#include <cuda_runtime.h>
#include <cuda_bf16.h>

// Fixed shapes from setup_inputs: B=128, N=10000, din=64, draw=64, T=8, D=128
#define B_MAX   128
#define N_MAX   10000
#define DIN     64
#define DMODL   128
#define RPB     400          // rows (n) per main block (float4-aligned)
#define MAXCH   32           // >= chunks = ceil(N/RPB) = 25

// Static scratch (no allocations allowed)
__device__ float g_E[(size_t)B_MAX * N_MAX];     // exp(e - m_chunk)
__device__ float g_pm[B_MAX * MAXCH];            // per-chunk masked max
__device__ float g_ps[B_MAX * MAXCH];            // per-chunk masked sum of exp
__device__ float g_scale[B_MAX * MAXCH];         // exp(m_chunk - m)/S

// ---------------------------------------------------------------------------
// main: one block per (b, chunk of 400 rows). Streams raw_x once.
//   phase 0: c[b] = dot(x[b,ni,:], a[t,0:64])        (L2-hot, redundant/block)
//   phase 1: e[n] = leaky(c + dot(raw_x[b,n,:], a[t,64:128])) -> smem
//   phase 2: m_chunk = max masked e; store exp(e-m_chunk); partial sums.
// ---------------------------------------------------------------------------
__global__ __launch_bounds__(256)
void main_kernel(const float* __restrict__ raw_x,
                 const float* __restrict__ x,
                 const float* __restrict__ a,
                 const float* __restrict__ adj_mask,
                 const int*   __restrict__ node_index,
                 const int*   __restrict__ type_index,
                 int N) {
    const int b     = blockIdx.y;
    const int chunk = blockIdx.x;
    const int tid   = threadIdx.x;
    const int warp  = tid >> 5;
    const int lane  = tid & 31;
    const int lane8 = lane & 7;
    const int grp   = lane >> 3;          // 0..3 : row within warp-iteration
    const int n0    = chunk * RPB;

    __shared__ float e_sm[RPB];
    __shared__ float red[64];
    __shared__ float bcast;

    const int t = type_index[b];

    // ---- phase 0: c[b] ----
    if (tid < 64) {
        int ni = node_index[0];
        red[tid] = x[((size_t)b * N + ni) * DIN + tid] * a[t * DMODL + tid];
    }
    __syncthreads();
    if (tid < 32) {
        float v = red[tid] + red[tid + 32];
        v += __shfl_xor_sync(0xffffffffu, v, 16);
        v += __shfl_xor_sync(0xffffffffu, v, 8);
        v += __shfl_xor_sync(0xffffffffu, v, 4);
        v += __shfl_xor_sync(0xffffffffu, v, 2);
        v += __shfl_xor_sync(0xffffffffu, v, 1);
        if (tid == 0) bcast = v;
    }
    __syncthreads();
    const float c = bcast;
    __syncthreads();     // bcast is rewritten in phase 2a; all must read first

    // ---- weights for this thread's 8 columns ----
    const float* ap = a + t * DMODL + DIN;
    const float4 wa = *reinterpret_cast<const float4*>(ap + lane8 * 4);
    const float4 wb = *reinterpret_cast<const float4*>(ap + 32 + lane8 * 4);

    const float* base = raw_x + (size_t)b * N * DIN;

    // ---- phase 1: 32 rows per block-iteration (4 per warp) ----
    const int ITERS = (RPB + 31) >> 5;    // 13
#pragma unroll 4
    for (int i = 0; i < ITERS; ++i) {
        int nl = i * 32 + warp * 4 + grp;
        bool valid = nl < RPB;
        float p = 0.f;
        if (valid) {
            const float* r = base + (size_t)(n0 + nl) * DIN;
            float4 va = *reinterpret_cast<const float4*>(r + lane8 * 4);
            float4 vb = *reinterpret_cast<const float4*>(r + 32 + lane8 * 4);
            p = va.x * wa.x + va.y * wa.y + va.z * wa.z + va.w * wa.w
              + vb.x * wb.x + vb.y * wb.y + vb.z * wb.z + vb.w * wb.w;
        }
        p += __shfl_xor_sync(0xffffffffu, p, 1);
        p += __shfl_xor_sync(0xffffffffu, p, 2);
        p += __shfl_xor_sync(0xffffffffu, p, 4);
        if (valid && lane8 == 0) {
            float e = c + p;
            e_sm[nl] = (e > 0.f) ? e : 0.01f * e;   // leaky relu
        }
    }
    __syncthreads();

    // ---- phase 2a: masked max over chunk ----
    const int nl0 = tid;
    const int nl1 = tid + 256;
    const bool has1 = nl1 < RPB;
    float m0 = adj_mask[n0 + nl0];
    float e0 = e_sm[nl0];
    float m1 = 0.f, e1 = 0.f;
    if (has1) { m1 = adj_mask[n0 + nl1]; e1 = e_sm[nl1]; }

    float lmax = (m0 > 0.f) ? e0 : -3.0e38f;
    if (has1 && m1 > 0.f) lmax = fmaxf(lmax, e1);

    lmax = fmaxf(lmax, __shfl_xor_sync(0xffffffffu, lmax, 16));
    lmax = fmaxf(lmax, __shfl_xor_sync(0xffffffffu, lmax, 8));
    lmax = fmaxf(lmax, __shfl_xor_sync(0xffffffffu, lmax, 4));
    lmax = fmaxf(lmax, __shfl_xor_sync(0xffffffffu, lmax, 2));
    lmax = fmaxf(lmax, __shfl_xor_sync(0xffffffffu, lmax, 1));
    if (lane == 0) red[warp] = lmax;
    __syncthreads();
    if (tid == 0) {
        float v = red[0];
#pragma unroll
        for (int i = 1; i < 8; ++i) v = fmaxf(v, red[i]);
        bcast = v;
    }
    __syncthreads();
    const float m_blk = bcast;

    // ---- phase 2b: exp, store, masked sum ----
    float s = 0.f;
    {
        float ex0 = __expf(e0 - m_blk);
        g_E[(size_t)b * N + n0 + nl0] = ex0;
        if (m0 > 0.f) s += ex0;
        if (has1) {
            float ex1 = __expf(e1 - m_blk);
            g_E[(size_t)b * N + n0 + nl1] = ex1;
            if (m1 > 0.f) s += ex1;
        }
    }
    s += __shfl_xor_sync(0xffffffffu, s, 16);
    s += __shfl_xor_sync(0xffffffffu, s, 8);
    s += __shfl_xor_sync(0xffffffffu, s, 4);
    s += __shfl_xor_sync(0xffffffffu, s, 2);
    s += __shfl_xor_sync(0xffffffffu, s, 1);
    if (lane == 0) red[32 + warp] = s;
    __syncthreads();
    if (tid == 0) {
        float tot = red[32];
#pragma unroll
        for (int i = 1; i < 8; ++i) tot += red[32 + i];
        g_pm[b * MAXCH + chunk] = m_blk;
        g_ps[b * MAXCH + chunk] = tot;
    }
}

// ---------------------------------------------------------------------------
// combine: per b reduce chunk partials -> per-chunk normalization scales.
// ---------------------------------------------------------------------------
__global__ void combine_kernel(int chunks) {
    const int b = blockIdx.x;
    const int lane = threadIdx.x;
    float pm = (lane < chunks) ? g_pm[b * MAXCH + lane] : -3.0e38f;
    float ps = (lane < chunks) ? g_ps[b * MAXCH + lane] : 0.f;

    float m = pm;
    m = fmaxf(m, __shfl_xor_sync(0xffffffffu, m, 16));
    m = fmaxf(m, __shfl_xor_sync(0xffffffffu, m, 8));
    m = fmaxf(m, __shfl_xor_sync(0xffffffffu, m, 4));
    m = fmaxf(m, __shfl_xor_sync(0xffffffffu, m, 2));
    m = fmaxf(m, __shfl_xor_sync(0xffffffffu, m, 1));

    float f = __expf(pm - m);          // 0 for empty/absent chunks
    float s = ps * f;
    s += __shfl_xor_sync(0xffffffffu, s, 16);
    s += __shfl_xor_sync(0xffffffffu, s, 8);
    s += __shfl_xor_sync(0xffffffffu, s, 4);
    s += __shfl_xor_sync(0xffffffffu, s, 2);
    s += __shfl_xor_sync(0xffffffffu, s, 1);

    if (lane < chunks) g_scale[b * MAXCH + lane] = f / s;
}

// ---------------------------------------------------------------------------
// norm: out = mask>0 ? g_E * scale[b,chunk] : 0.  Pure FMUL+select, float4.
// ---------------------------------------------------------------------------
__global__ __launch_bounds__(256)
void norm_kernel(const float* __restrict__ adj_mask,
                 float* __restrict__ out, int N) {
    const int b = blockIdx.y;
    const float4* E4 = reinterpret_cast<const float4*>(g_E + (size_t)b * N);
    const float4* M4 = reinterpret_cast<const float4*>(adj_mask);
    float4* O4 = reinterpret_cast<float4*>(out + (size_t)b * N);
    const int n4 = N >> 2;             // 2500

#pragma unroll
    for (int k = 0; k < 2; ++k) {
        int idx = blockIdx.x * 512 + k * 256 + threadIdx.x;
        if (idx < n4) {
            float4 e = E4[idx];
            float4 mm = M4[idx];
            float sc = g_scale[b * MAXCH + (idx * 4) / RPB];
            float4 o;
            o.x = (mm.x > 0.f) ? e.x * sc : 0.f;
            o.y = (mm.y > 0.f) ? e.y * sc : 0.f;
            o.z = (mm.z > 0.f) ? e.z * sc : 0.f;
            o.w = (mm.w > 0.f) ? e.w * sc : 0.f;
            O4[idx] = o;
        }
    }
}

// ---------------------------------------------------------------------------
extern "C" void kernel_launch(void* const* d_in, const int* in_sizes, int n_in,
                              void* d_out, int out_size) {
    const float* x          = (const float*)d_in[0];
    const float* raw_x      = (const float*)d_in[1];
    const float* a          = (const float*)d_in[2];
    const float* adj_mask   = (const float*)d_in[3];
    const int*   node_index = (const int*)  d_in[4];
    const int*   type_index = (const int*)  d_in[5];
    float* out = (float*)d_out;

    const int N = in_sizes[3];                 // adj_mask: (N,)
    const int B = in_sizes[5];                 // type_index: (B,)
    const int chunks = (N + RPB - 1) / RPB;    // 25

    main_kernel<<<dim3(chunks, B), 256>>>(raw_x, x, a, adj_mask,
                                          node_index, type_index, N);
    combine_kernel<<<B, 32>>>(chunks);

    const int n4 = N >> 2;
    norm_kernel<<<dim3((n4 + 511) / 512, B), 256>>>(adj_mask, out, N);
}